// round 2
// baseline (speedup 1.0000x reference)
#include <cuda_runtime.h>
#include <math.h>
#include <stdint.h>

// Problem constants
#define BSZ 2
#define NT  128
#define DM  512
#define NH  8
#define DHD 64
#define HIDD 2048
#define EPSC 1e-5f

#define HTOT (BSZ*NT*DM)                 // 131072
#define ETOT ((size_t)BSZ*NT*NT*DM)      // 16777216
#define UTOT ((size_t)BSZ*NT*NT*HIDD)    // 67108864

// ---------------- scratch (static device allocations; allocation-free rule) ----------------
__device__ float g_h1[HTOT];
__device__ float g_h2[HTOT];
__device__ float g_xh[HTOT];
__device__ float g_q[HTOT], g_k[HTOT], g_v[HTOT], g_ni[HTOT], g_nj[HTOT];
__device__ float g_ao[HTOT];
__device__ float g_uh[BSZ*NT*HIDD], g_th[BSZ*NT*HIDD];
__device__ float g_scale[DM], g_shift[DM];
__device__ float g_e1[ETOT];
__device__ float g_eW[ETOT];
__device__ float g_ev[ETOT];
__device__ float g_e2[ETOT];
__device__ float g_U[UTOT];
__device__ float g_T[UTOT];

// ---------------- BatchNorm: per-channel stats over (bs*n)=256 samples ----------------
__global__ void bn_stats(const float* __restrict__ x, const float* __restrict__ g,
                         const float* __restrict__ b, float* __restrict__ sc,
                         float* __restrict__ sh) {
    int c = blockIdx.x * blockDim.x + threadIdx.x;
    if (c >= DM) return;
    float s = 0.f, s2 = 0.f;
    #pragma unroll 4
    for (int i = 0; i < BSZ * NT; i++) {
        float v = x[(size_t)i * DM + c];
        s += v; s2 = fmaf(v, v, s2);
    }
    const float inv = 1.f / (BSZ * NT);
    float m = s * inv;
    float var = s2 * inv - m * m;
    float scale = g[c] / sqrtf(var + EPSC);
    sc[c] = scale;
    sh[c] = b[c] - m * scale;
}

__global__ void bn_apply(const float* __restrict__ x, float* __restrict__ y,
                         const float* __restrict__ sc, const float* __restrict__ sh, int n) {
    int i = blockIdx.x * blockDim.x + threadIdx.x;
    if (i < n) { int c = i & (DM - 1); y[i] = fmaf(x[i], sc[c], sh[c]); }
}

// ---------------- LayerNorm over last dim (512), one block (128 thr) per row ----------------
__global__ void ln_kernel(const float* __restrict__ x, float* __restrict__ y,
                          const float* __restrict__ g, const float* __restrict__ b) {
    int row = blockIdx.x;
    int t = threadIdx.x;  // 128 threads * float4 = 512
    const float4* xr = (const float4*)(x + (size_t)row * DM);
    float4 v = xr[t];
    float s  = v.x + v.y + v.z + v.w;
    float s2 = fmaf(v.x, v.x, fmaf(v.y, v.y, fmaf(v.z, v.z, v.w * v.w)));
    #pragma unroll
    for (int o = 16; o; o >>= 1) {
        s  += __shfl_xor_sync(0xffffffffu, s,  o);
        s2 += __shfl_xor_sync(0xffffffffu, s2, o);
    }
    __shared__ float sa[4], sb[4];
    if ((t & 31) == 0) { sa[t >> 5] = s; sb[t >> 5] = s2; }
    __syncthreads();
    s  = sa[0] + sa[1] + sa[2] + sa[3];
    s2 = sb[0] + sb[1] + sb[2] + sb[3];
    const float inv = 1.f / DM;
    float m  = s * inv;
    float var = s2 * inv - m * m;
    float rs = rsqrtf(var + EPSC);
    float4 gg = ((const float4*)g)[t];
    float4 bb = ((const float4*)b)[t];
    float4 o;
    o.x = fmaf((v.x - m) * rs, gg.x, bb.x);
    o.y = fmaf((v.y - m) * rs, gg.y, bb.y);
    o.z = fmaf((v.z - m) * rs, gg.z, bb.z);
    o.w = fmaf((v.w - m) * rs, gg.w, bb.w);
    ((float4*)(y + (size_t)row * DM))[t] = o;
}

// ---------------- SGEMM: C = A@B (+bias per col)(+add elementwise), row-major ----------------
// BM=BN=128, BK=8, 256 threads, 8x8 per thread. Requires M%128==0, N%128==0, K%8==0.
__global__ __launch_bounds__(256) void sgemm(
    const float* __restrict__ A, const float* __restrict__ B, float* __restrict__ C,
    int M, int N, int K, const float* __restrict__ bias, const float* __restrict__ add) {
    __shared__ float As[8][128];
    __shared__ float Bs[8][128];
    const int tid = threadIdx.x;
    const int bx = blockIdx.x, by = blockIdx.y;
    const int tx = tid & 15, ty = tid >> 4;
    const int a_row = tid >> 1, a_col = (tid & 1) * 4;
    const int b_row = tid >> 5, b_col = (tid & 31) * 4;

    const float* Ab = A + (size_t)(by * 128 + a_row) * K + a_col;
    const float* Bb = B + (size_t)b_row * N + bx * 128 + b_col;

    float acc[8][8];
    #pragma unroll
    for (int m = 0; m < 8; m++)
        #pragma unroll
        for (int n = 0; n < 8; n++) acc[m][n] = 0.f;

    for (int k0 = 0; k0 < K; k0 += 8) {
        float4 av = *(const float4*)(Ab + k0);
        As[a_col + 0][a_row] = av.x;
        As[a_col + 1][a_row] = av.y;
        As[a_col + 2][a_row] = av.z;
        As[a_col + 3][a_row] = av.w;
        *(float4*)(&Bs[b_row][b_col]) = *(const float4*)(Bb + (size_t)k0 * N);
        __syncthreads();
        #pragma unroll
        for (int kk = 0; kk < 8; kk++) {
            float ar[8], br[8];
            #pragma unroll
            for (int m = 0; m < 8; m++) ar[m] = As[kk][ty * 8 + m];
            #pragma unroll
            for (int n = 0; n < 8; n++) br[n] = Bs[kk][tx * 8 + n];
            #pragma unroll
            for (int m = 0; m < 8; m++)
                #pragma unroll
                for (int n = 0; n < 8; n++) acc[m][n] = fmaf(ar[m], br[n], acc[m][n]);
        }
        __syncthreads();
    }
    #pragma unroll
    for (int m = 0; m < 8; m++) {
        int row = by * 128 + ty * 8 + m;
        int col0 = bx * 128 + tx * 8;
        float* crow = C + (size_t)row * N + col0;
        #pragma unroll
        for (int n = 0; n < 8; n++) {
            float v = acc[m][n];
            if (bias) v += bias[col0 + n];
            if (add)  v += add[(size_t)row * N + col0 + n];
            crow[n] = v;
        }
    }
}

// ---------------- ev = eW + ni (bcast over j) + nj (bcast over i) ----------------
__global__ void ev_add() {
    size_t i4 = (size_t)blockIdx.x * blockDim.x + threadIdx.x;
    if (i4 >= ETOT / 4) return;
    size_t idx = i4 * 4;
    int d = (int)(idx % DM);
    size_t r = idx / DM;
    int j = (int)(r % NT); r /= NT;
    int i = (int)(r % NT);
    int b = (int)(r / NT);
    float4 ew = *(const float4*)&g_eW[idx];
    float4 a  = *(const float4*)&g_ni[(size_t)(b * NT + i) * DM + d];
    float4 c  = *(const float4*)&g_nj[(size_t)(b * NT + j) * DM + d];
    float4 o = {ew.x + a.x + c.x, ew.y + a.y + c.y, ew.z + a.z + c.z, ew.w + a.w + c.w};
    *(float4*)&g_ev[idx] = o;
}

// ---------------- attention: one block per (b,h,i), 128 threads (one per j) ----------------
__global__ void attn_kernel() {
    int i = blockIdx.x % NT;
    int h = (blockIdx.x / NT) % NH;
    int b = blockIdx.x / (NT * NH);
    int t = threadIdx.x;  // = j
    __shared__ float qs[DHD];
    __shared__ float scs[NT];
    __shared__ float red[4];

    if (t < DHD) qs[t] = g_q[(size_t)(b * NT + i) * DM + h * DHD + t];
    __syncthreads();

    const float* evrow = g_ev + ((size_t)(b * NT + i) * NT + t) * DM + h * DHD;
    const float* krow  = g_k + (size_t)(b * NT + t) * DM + h * DHD;
    float s = 0.f;
    #pragma unroll 8
    for (int d = 0; d < DHD; d++) s = fmaf(qs[d] * evrow[d], krow[d], s);
    s *= 0.125f;  // 1/sqrt(64)

    // softmax over j (128 threads)
    float m = s;
    #pragma unroll
    for (int o = 16; o; o >>= 1) m = fmaxf(m, __shfl_xor_sync(0xffffffffu, m, o));
    if ((t & 31) == 0) red[t >> 5] = m;
    __syncthreads();
    m = fmaxf(fmaxf(red[0], red[1]), fmaxf(red[2], red[3]));
    float p = expf(s - m);
    float ssum = p;
    #pragma unroll
    for (int o = 16; o; o >>= 1) ssum += __shfl_xor_sync(0xffffffffu, ssum, o);
    __syncthreads();   // red reuse
    if ((t & 31) == 0) red[t >> 5] = ssum;
    __syncthreads();
    ssum = red[0] + red[1] + red[2] + red[3];
    scs[t] = p / ssum;
    __syncthreads();

    if (t < DHD) {
        float o = 0.f;
        #pragma unroll 8
        for (int j = 0; j < NT; j++)
            o = fmaf(scs[j], g_v[(size_t)(b * NT + j) * DM + h * DHD + t], o);
        g_ao[(size_t)(b * NT + i) * DM + h * DHD + t] = o;
    }
}

// ---------------- swiglu elementwise: u = silu(u) * t ----------------
__global__ void silu_mul(float4* __restrict__ u, const float4* __restrict__ t, size_t n4) {
    size_t i = (size_t)blockIdx.x * blockDim.x + threadIdx.x;
    if (i >= n4) return;
    float4 a = u[i], b = t[i];
    a.x = a.x / (1.f + expf(-a.x)) * b.x;
    a.y = a.y / (1.f + expf(-a.y)) * b.y;
    a.z = a.z / (1.f + expf(-a.z)) * b.z;
    a.w = a.w / (1.f + expf(-a.w)) * b.w;
    u[i] = a;
}

// ---------------- sym_tensor: lower triangle <- upper transposed where |upper|>0 ----------------
__global__ void sym_kernel(float* __restrict__ out) {
    size_t i4 = (size_t)blockIdx.x * blockDim.x + threadIdx.x;
    if (i4 >= ETOT / 4) return;
    size_t idx = i4 * 4;
    int d = (int)(idx % DM);
    size_t r = idx / DM;
    int j = (int)(r % NT); r /= NT;
    int i = (int)(r % NT);
    int b = (int)(r / NT);
    float4 v = *(const float4*)&g_e2[idx];
    if (i > j) {
        float4 u = *(const float4*)&g_e2[((size_t)(b * NT + j) * NT + i) * DM + d];
        if (fabsf(u.x) > 0.f) v.x = u.x;
        if (fabsf(u.y) > 0.f) v.y = u.y;
        if (fabsf(u.z) > 0.f) v.z = u.z;
        if (fabsf(u.w) > 0.f) v.w = u.w;
    }
    *(float4*)&out[idx] = v;
}

// ---------------- host launch ----------------
extern "C" void kernel_launch(void* const* d_in, const int* in_sizes, int n_in,
                              void* d_out, int out_size) {
    const float* h      = (const float*)d_in[0];
    const float* e      = (const float*)d_in[1];
    const float* Wq     = (const float*)d_in[2];
    const float* Wk     = (const float*)d_in[3];
    const float* Wv     = (const float*)d_in[4];
    const float* We     = (const float*)d_in[5];
    const float* Wni    = (const float*)d_in[6];
    const float* Wnj    = (const float*)d_in[7];
    const float* Woh    = (const float*)d_in[8];
    const float* boh    = (const float*)d_in[9];
    const float* Woe    = (const float*)d_in[10];
    const float* boe    = (const float*)d_in[11];
    const float* bn1_g  = (const float*)d_in[12];
    const float* bn1_b  = (const float*)d_in[13];
    const float* bn2_g  = (const float*)d_in[14];
    const float* bn2_b  = (const float*)d_in[15];
    const float* ln1_g  = (const float*)d_in[16];
    const float* ln1_b  = (const float*)d_in[17];
    const float* ln2_g  = (const float*)d_in[18];
    const float* ln2_b  = (const float*)d_in[19];
    const float* ffh_w1 = (const float*)d_in[20];
    const float* ffh_w3 = (const float*)d_in[21];
    const float* ffh_w2 = (const float*)d_in[22];
    const float* ffe_w1 = (const float*)d_in[23];
    const float* ffe_w3 = (const float*)d_in[24];
    const float* ffe_w2 = (const float*)d_in[25];
    float* out = (float*)d_out;

    float *h1, *h2, *xh, *q, *k, *v, *ni, *nj, *ao, *uh, *th, *sc, *sh;
    float *e1, *eW, *ev, *e2, *U, *T;
    cudaGetSymbolAddress((void**)&h1, g_h1);
    cudaGetSymbolAddress((void**)&h2, g_h2);
    cudaGetSymbolAddress((void**)&xh, g_xh);
    cudaGetSymbolAddress((void**)&q,  g_q);
    cudaGetSymbolAddress((void**)&k,  g_k);
    cudaGetSymbolAddress((void**)&v,  g_v);
    cudaGetSymbolAddress((void**)&ni, g_ni);
    cudaGetSymbolAddress((void**)&nj, g_nj);
    cudaGetSymbolAddress((void**)&ao, g_ao);
    cudaGetSymbolAddress((void**)&uh, g_uh);
    cudaGetSymbolAddress((void**)&th, g_th);
    cudaGetSymbolAddress((void**)&sc, g_scale);
    cudaGetSymbolAddress((void**)&sh, g_shift);
    cudaGetSymbolAddress((void**)&e1, g_e1);
    cudaGetSymbolAddress((void**)&eW, g_eW);
    cudaGetSymbolAddress((void**)&ev, g_ev);
    cudaGetSymbolAddress((void**)&e2, g_e2);
    cudaGetSymbolAddress((void**)&U,  g_U);
    cudaGetSymbolAddress((void**)&T,  g_T);

    const int NROWS_E = BSZ * NT * NT;  // 32768

    // h1 = bn1(h); e1 = ln1(e)
    bn_stats<<<2, 256>>>(h, bn1_g, bn1_b, sc, sh);
    bn_apply<<<HTOT / 256, 256>>>(h, h1, sc, sh, HTOT);
    ln_kernel<<<NROWS_E, 128>>>(e, e1, ln1_g, ln1_b);

    // projections
    dim3 gs(4, 2);  // N=512, M=256
    sgemm<<<gs, 256>>>(h1, Wq,  q,  256, 512, 512, nullptr, nullptr);
    sgemm<<<gs, 256>>>(h1, Wk,  k,  256, 512, 512, nullptr, nullptr);
    sgemm<<<gs, 256>>>(h1, Wv,  v,  256, 512, 512, nullptr, nullptr);
    sgemm<<<gs, 256>>>(h1, Wni, ni, 256, 512, 512, nullptr, nullptr);
    sgemm<<<gs, 256>>>(h1, Wnj, nj, 256, 512, 512, nullptr, nullptr);

    dim3 ge(4, 256);  // N=512, M=32768
    sgemm<<<ge, 256>>>(e1, We, eW, NROWS_E, 512, 512, nullptr, nullptr);
    ev_add<<<(int)(ETOT / 4 / 256), 256>>>();

    // attention
    attn_kernel<<<BSZ * NH * NT, 128>>>();

    // h2 = h1 + ao@Woh + boh ;  e2 = e1 + ev@Woe + boe
    sgemm<<<gs, 256>>>(ao, Woh, h2, 256, 512, 512, boh, h1);
    sgemm<<<ge, 256>>>(ev, Woe, e2, NROWS_E, 512, 512, boe, e1);

    // node FFN: h_out = h2 + swiglu(bn2(h2))
    bn_stats<<<2, 256>>>(h2, bn2_g, bn2_b, sc, sh);
    bn_apply<<<HTOT / 256, 256>>>(h2, xh, sc, sh, HTOT);
    dim3 gh(16, 2);  // N=2048, M=256
    sgemm<<<gh, 256>>>(xh, ffh_w1, uh, 256, 2048, 512, nullptr, nullptr);
    sgemm<<<gh, 256>>>(xh, ffh_w3, th, 256, 2048, 512, nullptr, nullptr);
    silu_mul<<<(BSZ * NT * HIDD / 4) / 256, 256>>>((float4*)uh, (const float4*)th,
                                                   (size_t)BSZ * NT * HIDD / 4);
    sgemm<<<gs, 256>>>(uh, ffh_w2, out, 256, 512, 2048, nullptr, h2);  // final h -> d_out

    // edge FFN: e2 += swiglu(ln2(e2))
    ln_kernel<<<NROWS_E, 128>>>(e2, e1, ln2_g, ln2_b);  // reuse e1 as xe
    dim3 gu(16, 256);  // N=2048, M=32768
    sgemm<<<gu, 256>>>(e1, ffe_w1, U, NROWS_E, 2048, 512, nullptr, nullptr);
    sgemm<<<gu, 256>>>(e1, ffe_w3, T, NROWS_E, 2048, 512, nullptr, nullptr);
    silu_mul<<<(int)(UTOT / 4 / 256), 256>>>((float4*)U, (const float4*)T, UTOT / 4);
    sgemm<<<ge, 256>>>(U, ffe_w2, e2, NROWS_E, 512, 2048, nullptr, e2);  // in-place residual

    // sym tensor into d_out (after h block of 131072 floats)
    sym_kernel<<<(int)(ETOT / 4 / 256), 256>>>(out + HTOT);
}

// round 4
// speedup vs baseline: 2.4865x; 2.4865x over previous
#include <cuda_runtime.h>
#include <cuda_bf16.h>
#include <math.h>
#include <stdint.h>

// Problem constants
#define BSZ 2
#define NT  128
#define DM  512
#define NH  8
#define DHD 64
#define HIDD 2048
#define EPSC 1e-5f

#define HTOT (BSZ*NT*DM)                 // 131072
#define EROWS (BSZ*NT*NT)                // 32768
#define ETOT ((size_t)EROWS*DM)          // 16777216
#define QKVW 2560
#define WPOOL 8388608

// ---------------- scratch (static device allocations) ----------------
__device__ float g_h1[HTOT];
__device__ float g_h2[HTOT];
__device__ float g_qkv[BSZ*NT*QKVW];
__device__ float g_ao[HTOT];
__device__ float g_uth[BSZ*NT*2*HIDD];
__device__ float g_scale[DM], g_shift[DM];
__device__ float g_e1[(size_t)EROWS*DM];
__device__ float g_eW[(size_t)EROWS*DM];
__device__ float g_ev[(size_t)EROWS*DM];
__device__ float g_e2[(size_t)EROWS*DM];
__device__ float g_UT[(size_t)EROWS*2*HIDD];   // [U|T] per row (4096)

__device__ __nv_bfloat16 g_e1hi[(size_t)EROWS*DM], g_e1lo[(size_t)EROWS*DM];
__device__ __nv_bfloat16 g_evhi[(size_t)EROWS*DM], g_evlo[(size_t)EROWS*DM];
__device__ __nv_bfloat16 g_Shi[(size_t)EROWS*HIDD], g_Slo[(size_t)EROWS*HIDD];
__device__ __nv_bfloat16 g_h1hi[HTOT], g_h1lo[HTOT];
__device__ __nv_bfloat16 g_aohi[HTOT], g_aolo[HTOT];
__device__ __nv_bfloat16 g_xhhi[HTOT], g_xhlo[HTOT];
__device__ __nv_bfloat16 g_shhi[BSZ*NT*HIDD], g_shlo[BSZ*NT*HIDD];
__device__ __nv_bfloat16 g_whi[WPOOL], g_wlo[WPOOL];

// ---------------- helpers ----------------
__device__ __forceinline__ uint32_t smem_u32(const void* p) {
    uint32_t a;
    asm("{ .reg .u64 t; cvta.to.shared.u64 t, %1; cvt.u32.u64 %0, t; }" : "=r"(a) : "l"(p));
    return a;
}
__device__ __forceinline__ void ldsm_x4(uint32_t* r, uint32_t addr) {
    asm volatile("ldmatrix.sync.aligned.m8n8.x4.shared.b16 {%0,%1,%2,%3}, [%4];"
                 : "=r"(r[0]), "=r"(r[1]), "=r"(r[2]), "=r"(r[3]) : "r"(addr));
}
__device__ __forceinline__ void mma_bf16(float* d, const uint32_t* a, uint32_t b0, uint32_t b1) {
    asm volatile(
        "mma.sync.aligned.m16n8k16.row.col.f32.bf16.bf16.f32 "
        "{%0,%1,%2,%3}, {%4,%5,%6,%7}, {%8,%9}, {%0,%1,%2,%3};"
        : "+f"(d[0]), "+f"(d[1]), "+f"(d[2]), "+f"(d[3])
        : "r"(a[0]), "r"(a[1]), "r"(a[2]), "r"(a[3]), "r"(b0), "r"(b1));
}
__device__ __forceinline__ void split2(float v, __nv_bfloat16* hi, __nv_bfloat16* lo) {
    __nv_bfloat16 h = __float2bfloat16_rn(v);
    *hi = h;
    *lo = __float2bfloat16_rn(v - __bfloat162float(h));
}

// ---------------- mma.sync GEMM: C[M,N] = sum_k A[M,K]*B[N,K]  (B is W^T) ----------------
// hi/lo bf16 split operands, 3 accumulation passes into the same accumulators.
// BM=BN=128, BK=32, 256 threads (8 warps: 4 m x 2 n), warp tile 32x64, double-buffered smem.
#define PADR 40   // smem row stride in bf16 elements (80 bytes)

__global__ __launch_bounds__(256) void tc_gemm(
    const __nv_bfloat16* __restrict__ Ahi, const __nv_bfloat16* __restrict__ Alo,
    const __nv_bfloat16* __restrict__ Bhi, const __nv_bfloat16* __restrict__ Blo,
    float* __restrict__ C, int M, int N, int K,
    const float* __restrict__ bias, const float* __restrict__ add)
{
    __shared__ __nv_bfloat16 sA[2][128 * PADR];
    __shared__ __nv_bfloat16 sB[2][128 * PADR];

    const int tid = threadIdx.x, lane = tid & 31, wid = tid >> 5;
    const int warp_m = wid & 3, warp_n = wid >> 2;
    const int m0 = blockIdx.y * 128, n0 = blockIdx.x * 128;
    const int kch = K >> 5;      // BK=32 chunks per pass
    const int total = 3 * kch;

    const int lr = tid >> 2;     // 0..63 (rows; +64 for second slot)
    const int lg = tid & 3;      // k-group of 8

    float acc[2][8][4];
    #pragma unroll
    for (int s = 0; s < 2; s++)
        #pragma unroll
        for (int f = 0; f < 8; f++)
            #pragma unroll
            for (int u = 0; u < 4; u++) acc[s][f][u] = 0.f;

    uint4 pa[2], pb[2];
    auto LOADREGS = [&](int it) {
        int pass = it / kch, kc = it - pass * kch;
        const __nv_bfloat16* Ap = (pass == 1) ? Alo : Ahi;
        const __nv_bfloat16* Bp = (pass == 2) ? Blo : Bhi;
        const __nv_bfloat16* ab = Ap + (size_t)(m0 + lr) * K + kc * 32 + lg * 8;
        pa[0] = *(const uint4*)ab;
        pa[1] = *(const uint4*)(ab + (size_t)64 * K);
        const __nv_bfloat16* bb = Bp + (size_t)(n0 + lr) * K + kc * 32 + lg * 8;
        pb[0] = *(const uint4*)bb;
        pb[1] = *(const uint4*)(bb + (size_t)64 * K);
    };
    auto STORESM = [&](int buf) {
        *(uint4*)&sA[buf][lr * PADR + lg * 8] = pa[0];
        *(uint4*)&sA[buf][(lr + 64) * PADR + lg * 8] = pa[1];
        *(uint4*)&sB[buf][lr * PADR + lg * 8] = pb[0];
        *(uint4*)&sB[buf][(lr + 64) * PADR + lg * 8] = pb[1];
    };

    const uint32_t aBase = smem_u32(&sA[0][0]);
    const uint32_t bBase = smem_u32(&sB[0][0]);
    const uint32_t BUFB = 128 * PADR * 2;  // bytes per buffer
    const uint32_t aoff = ((warp_m * 32 + (lane & 15)) * PADR + (lane >> 4) * 8) * 2;
    const uint32_t boff = ((warp_n * 64 + (lane & 15)) * PADR + (lane >> 4) * 8) * 2;

    LOADREGS(0);
    STORESM(0);
    __syncthreads();

    for (int it = 0; it < total; ++it) {
        const int buf = it & 1;
        if (it + 1 < total) LOADREGS(it + 1);

        const uint32_t ab = aBase + buf * BUFB + aoff;
        const uint32_t bb = bBase + buf * BUFB + boff;
        #pragma unroll
        for (int kk = 0; kk < 32; kk += 16) {
            uint32_t A0[4], A1[4], Bf[4][4];
            ldsm_x4(A0, ab + kk * 2);
            ldsm_x4(A1, ab + kk * 2 + 16 * PADR * 2);
            #pragma unroll
            for (int g = 0; g < 4; g++) ldsm_x4(Bf[g], bb + kk * 2 + g * 16 * PADR * 2);
            #pragma unroll
            for (int fn = 0; fn < 8; fn++) {
                uint32_t b0 = Bf[fn >> 1][fn & 1];
                uint32_t b1 = Bf[fn >> 1][(fn & 1) + 2];
                mma_bf16(acc[0][fn], A0, b0, b1);
                mma_bf16(acc[1][fn], A1, b0, b1);
            }
        }
        __syncthreads();
        if (it + 1 < total) {
            STORESM(buf ^ 1);
            __syncthreads();
        }
    }

    // epilogue
    #pragma unroll
    for (int s = 0; s < 2; s++) {
        int ra = m0 + warp_m * 32 + s * 16 + (lane >> 2);
        int rb = ra + 8;
        #pragma unroll
        for (int fn = 0; fn < 8; fn++) {
            int cb = n0 + warp_n * 64 + fn * 8 + (lane & 3) * 2;
            float2 v0 = {acc[s][fn][0], acc[s][fn][1]};
            float2 v1 = {acc[s][fn][2], acc[s][fn][3]};
            if (bias) {
                float2 bv = *(const float2*)(bias + cb);
                v0.x += bv.x; v0.y += bv.y;
                v1.x += bv.x; v1.y += bv.y;
            }
            if (add) {
                float2 a0 = *(const float2*)(add + (size_t)ra * N + cb);
                float2 a1 = *(const float2*)(add + (size_t)rb * N + cb);
                v0.x += a0.x; v0.y += a0.y;
                v1.x += a1.x; v1.y += a1.y;
            }
            *(float2*)(C + (size_t)ra * N + cb) = v0;
            *(float2*)(C + (size_t)rb * N + cb) = v1;
        }
    }
}

// ---------------- weight transpose + split: w[K,N] fp32 -> hi/lo[N,K] bf16 ----------------
__global__ void wcvt(const float* __restrict__ w, __nv_bfloat16* __restrict__ hi,
                     __nv_bfloat16* __restrict__ lo, int K, int N) {
    __shared__ float t[32][33];
    int kb = blockIdx.y * 32, nb = blockIdx.x * 32;
    int tx = threadIdx.x, ty = threadIdx.y;  // 32x8
    #pragma unroll
    for (int i = 0; i < 32; i += 8)
        t[ty + i][tx] = w[(size_t)(kb + ty + i) * N + nb + tx];
    __syncthreads();
    #pragma unroll
    for (int i = 0; i < 32; i += 8) {
        float v = t[tx][ty + i];
        size_t o = (size_t)(nb + ty + i) * K + kb + tx;
        __nv_bfloat16 h, l;
        split2(v, &h, &l);
        hi[o] = h; lo[o] = l;
    }
}

// ---------------- BatchNorm ----------------
__global__ void bn_stats(const float* __restrict__ x, const float* __restrict__ g,
                         const float* __restrict__ b) {
    int c = blockIdx.x * blockDim.x + threadIdx.x;
    if (c >= DM) return;
    float s = 0.f, s2 = 0.f;
    #pragma unroll 4
    for (int i = 0; i < BSZ * NT; i++) {
        float v = x[(size_t)i * DM + c];
        s += v; s2 = fmaf(v, v, s2);
    }
    const float inv = 1.f / (BSZ * NT);
    float m = s * inv;
    float var = s2 * inv - m * m;
    float scale = g[c] / sqrtf(var + EPSC);
    g_scale[c] = scale;
    g_shift[c] = b[c] - m * scale;
}

__global__ void bn_apply_cvt(const float* __restrict__ x, float* __restrict__ y,
                             __nv_bfloat16* __restrict__ hi, __nv_bfloat16* __restrict__ lo) {
    int i = blockIdx.x * blockDim.x + threadIdx.x;  // over HTOT/4
    if (i >= HTOT / 4) return;
    int idx = i * 4;
    int c = idx & (DM - 1);
    float4 v = *(const float4*)(x + idx);
    float4 o;
    o.x = fmaf(v.x, g_scale[c + 0], g_shift[c + 0]);
    o.y = fmaf(v.y, g_scale[c + 1], g_shift[c + 1]);
    o.z = fmaf(v.z, g_scale[c + 2], g_shift[c + 2]);
    o.w = fmaf(v.w, g_scale[c + 3], g_shift[c + 3]);
    if (y) *(float4*)(y + idx) = o;
    __nv_bfloat16 h0, l0, h1, l1, h2, l2, h3, l3;
    split2(o.x, &h0, &l0); split2(o.y, &h1, &l1);
    split2(o.z, &h2, &l2); split2(o.w, &h3, &l3);
    ushort4 hv = {__bfloat16_as_ushort(h0), __bfloat16_as_ushort(h1),
                  __bfloat16_as_ushort(h2), __bfloat16_as_ushort(h3)};
    ushort4 lv = {__bfloat16_as_ushort(l0), __bfloat16_as_ushort(l1),
                  __bfloat16_as_ushort(l2), __bfloat16_as_ushort(l3)};
    *(ushort4*)(hi + idx) = hv;
    *(ushort4*)(lo + idx) = lv;
}

// ---------------- LayerNorm (+ optional fp32 out, + hi/lo split) ----------------
__global__ void ln_cvt(const float* __restrict__ x, float* __restrict__ y,
                       __nv_bfloat16* __restrict__ hi, __nv_bfloat16* __restrict__ lo,
                       const float* __restrict__ g, const float* __restrict__ b) {
    int row = blockIdx.x;
    int t = threadIdx.x;  // 128
    const float4* xr = (const float4*)(x + (size_t)row * DM);
    float4 v = xr[t];
    float s  = v.x + v.y + v.z + v.w;
    float s2 = fmaf(v.x, v.x, fmaf(v.y, v.y, fmaf(v.z, v.z, v.w * v.w)));
    #pragma unroll
    for (int o = 16; o; o >>= 1) {
        s  += __shfl_xor_sync(0xffffffffu, s,  o);
        s2 += __shfl_xor_sync(0xffffffffu, s2, o);
    }
    __shared__ float sa[4], sbx[4];
    if ((t & 31) == 0) { sa[t >> 5] = s; sbx[t >> 5] = s2; }
    __syncthreads();
    s  = sa[0] + sa[1] + sa[2] + sa[3];
    s2 = sbx[0] + sbx[1] + sbx[2] + sbx[3];
    const float inv = 1.f / DM;
    float m  = s * inv;
    float var = s2 * inv - m * m;
    float rs = rsqrtf(var + EPSC);
    float4 gg = ((const float4*)g)[t];
    float4 bb = ((const float4*)b)[t];
    float4 o;
    o.x = fmaf((v.x - m) * rs, gg.x, bb.x);
    o.y = fmaf((v.y - m) * rs, gg.y, bb.y);
    o.z = fmaf((v.z - m) * rs, gg.z, bb.z);
    o.w = fmaf((v.w - m) * rs, gg.w, bb.w);
    size_t idx = (size_t)row * DM + t * 4;
    if (y) *(float4*)(y + idx) = o;
    __nv_bfloat16 h0, l0, h1, l1, h2, l2, h3, l3;
    split2(o.x, &h0, &l0); split2(o.y, &h1, &l1);
    split2(o.z, &h2, &l2); split2(o.w, &h3, &l3);
    ushort4 hv = {__bfloat16_as_ushort(h0), __bfloat16_as_ushort(h1),
                  __bfloat16_as_ushort(h2), __bfloat16_as_ushort(h3)};
    ushort4 lv = {__bfloat16_as_ushort(l0), __bfloat16_as_ushort(l1),
                  __bfloat16_as_ushort(l2), __bfloat16_as_ushort(l3)};
    *(ushort4*)(hi + idx) = hv;
    *(ushort4*)(lo + idx) = lv;
}

// ---------------- ev = eW + ni + nj (ni/nj inside qkv buffer), + hi/lo ----------------
__global__ void ev_add_cvt() {
    size_t i4 = (size_t)blockIdx.x * blockDim.x + threadIdx.x;
    if (i4 >= ETOT / 4) return;
    size_t idx = i4 * 4;
    int d = (int)(idx % DM);
    size_t r = idx / DM;
    int j = (int)(r % NT); r /= NT;
    int i = (int)(r % NT);
    int b = (int)(r / NT);
    float4 ew = *(const float4*)&g_eW[idx];
    float4 a  = *(const float4*)&g_qkv[(size_t)(b * NT + i) * QKVW + 3 * DM + d];
    float4 c  = *(const float4*)&g_qkv[(size_t)(b * NT + j) * QKVW + 4 * DM + d];
    float4 o = {ew.x + a.x + c.x, ew.y + a.y + c.y, ew.z + a.z + c.z, ew.w + a.w + c.w};
    *(float4*)&g_ev[idx] = o;
    __nv_bfloat16 h0, l0, h1, l1, h2, l2, h3, l3;
    split2(o.x, &h0, &l0); split2(o.y, &h1, &l1);
    split2(o.z, &h2, &l2); split2(o.w, &h3, &l3);
    ushort4 hv = {__bfloat16_as_ushort(h0), __bfloat16_as_ushort(h1),
                  __bfloat16_as_ushort(h2), __bfloat16_as_ushort(h3)};
    ushort4 lv = {__bfloat16_as_ushort(l0), __bfloat16_as_ushort(l1),
                  __bfloat16_as_ushort(l2), __bfloat16_as_ushort(l3)};
    *(ushort4*)(g_evhi + idx) = hv;
    *(ushort4*)(g_evlo + idx) = lv;
}

// ---------------- attention: one block per (b,h,i), 128 threads ----------------
__global__ void attn_kernel() {
    int i = blockIdx.x % NT;
    int h = (blockIdx.x / NT) % NH;
    int b = blockIdx.x / (NT * NH);
    int t = threadIdx.x;  // = j
    __shared__ float qs[DHD];
    __shared__ float scs[NT];
    __shared__ float red[4];

    if (t < DHD) qs[t] = g_qkv[(size_t)(b * NT + i) * QKVW + h * DHD + t];
    __syncthreads();

    const float* evrow = g_ev + ((size_t)(b * NT + i) * NT + t) * DM + h * DHD;
    const float* krow  = g_qkv + (size_t)(b * NT + t) * QKVW + DM + h * DHD;
    float s = 0.f;
    #pragma unroll 8
    for (int d = 0; d < DHD; d++) s = fmaf(qs[d] * evrow[d], krow[d], s);
    s *= 0.125f;

    float m = s;
    #pragma unroll
    for (int o = 16; o; o >>= 1) m = fmaxf(m, __shfl_xor_sync(0xffffffffu, m, o));
    if ((t & 31) == 0) red[t >> 5] = m;
    __syncthreads();
    m = fmaxf(fmaxf(red[0], red[1]), fmaxf(red[2], red[3]));
    float p = expf(s - m);
    float ssum = p;
    #pragma unroll
    for (int o = 16; o; o >>= 1) ssum += __shfl_xor_sync(0xffffffffu, ssum, o);
    __syncthreads();
    if ((t & 31) == 0) red[t >> 5] = ssum;
    __syncthreads();
    ssum = red[0] + red[1] + red[2] + red[3];
    scs[t] = p / ssum;
    __syncthreads();

    if (t < DHD) {
        float o = 0.f;
        #pragma unroll 8
        for (int j = 0; j < NT; j++)
            o = fmaf(scs[j], g_qkv[(size_t)(b * NT + j) * QKVW + 2 * DM + h * DHD + t], o);
        g_ao[(size_t)(b * NT + i) * DM + h * DHD + t] = o;
    }
}

// ---------------- generic fp32 -> hi/lo split ----------------
__global__ void cvt_split(const float* __restrict__ x, __nv_bfloat16* __restrict__ hi,
                          __nv_bfloat16* __restrict__ lo, size_t n4) {
    size_t i = (size_t)blockIdx.x * blockDim.x + threadIdx.x;
    if (i >= n4) return;
    float4 v = *(const float4*)(x + i * 4);
    __nv_bfloat16 h0, l0, h1, l1, h2, l2, h3, l3;
    split2(v.x, &h0, &l0); split2(v.y, &h1, &l1);
    split2(v.z, &h2, &l2); split2(v.w, &h3, &l3);
    ushort4 hv = {__bfloat16_as_ushort(h0), __bfloat16_as_ushort(h1),
                  __bfloat16_as_ushort(h2), __bfloat16_as_ushort(h3)};
    ushort4 lv = {__bfloat16_as_ushort(l0), __bfloat16_as_ushort(l1),
                  __bfloat16_as_ushort(l2), __bfloat16_as_ushort(l3)};
    *(ushort4*)(hi + i * 4) = hv;
    *(ushort4*)(lo + i * 4) = lv;
}

// ---------------- silu(u)*t from [U|T] rows of 4096, -> hi/lo bf16 [rows,2048] ----------------
__global__ void silu_cvt(const float* __restrict__ ut, __nv_bfloat16* __restrict__ hi,
                         __nv_bfloat16* __restrict__ lo, size_t rows) {
    size_t i = (size_t)blockIdx.x * blockDim.x + threadIdx.x;  // over rows*512 float4s
    if (i >= rows * 512) return;
    size_t r = i / 512;
    int c4 = (int)(i % 512);
    float4 u = *(const float4*)(ut + r * 4096 + c4 * 4);
    float4 t = *(const float4*)(ut + r * 4096 + 2048 + c4 * 4);
    float4 s;
    s.x = u.x / (1.f + expf(-u.x)) * t.x;
    s.y = u.y / (1.f + expf(-u.y)) * t.y;
    s.z = u.z / (1.f + expf(-u.z)) * t.z;
    s.w = u.w / (1.f + expf(-u.w)) * t.w;
    __nv_bfloat16 h0, l0, h1, l1, h2, l2, h3, l3;
    split2(s.x, &h0, &l0); split2(s.y, &h1, &l1);
    split2(s.z, &h2, &l2); split2(s.w, &h3, &l3);
    ushort4 hv = {__bfloat16_as_ushort(h0), __bfloat16_as_ushort(h1),
                  __bfloat16_as_ushort(h2), __bfloat16_as_ushort(h3)};
    ushort4 lv = {__bfloat16_as_ushort(l0), __bfloat16_as_ushort(l1),
                  __bfloat16_as_ushort(l2), __bfloat16_as_ushort(l3)};
    size_t o = r * 2048 + c4 * 4;
    *(ushort4*)(hi + o) = hv;
    *(ushort4*)(lo + o) = lv;
}

// ---------------- sym_tensor ----------------
__global__ void sym_kernel(float* __restrict__ out) {
    size_t i4 = (size_t)blockIdx.x * blockDim.x + threadIdx.x;
    if (i4 >= ETOT / 4) return;
    size_t idx = i4 * 4;
    int d = (int)(idx % DM);
    size_t r = idx / DM;
    int j = (int)(r % NT); r /= NT;
    int i = (int)(r % NT);
    int b = (int)(r / NT);
    float4 v = *(const float4*)&g_eW[idx];
    if (i > j) {
        float4 u = *(const float4*)&g_eW[((size_t)(b * NT + j) * NT + i) * DM + d];
        if (fabsf(u.x) > 0.f) v.x = u.x;
        if (fabsf(u.y) > 0.f) v.y = u.y;
        if (fabsf(u.z) > 0.f) v.z = u.z;
        if (fabsf(u.w) > 0.f) v.w = u.w;
    }
    *(float4*)&out[idx] = v;
}

// ---------------- host launch ----------------
extern "C" void kernel_launch(void* const* d_in, const int* in_sizes, int n_in,
                              void* d_out, int out_size) {
    const float* h      = (const float*)d_in[0];
    const float* e      = (const float*)d_in[1];
    const float* Wq     = (const float*)d_in[2];
    const float* Wk     = (const float*)d_in[3];
    const float* Wv     = (const float*)d_in[4];
    const float* We     = (const float*)d_in[5];
    const float* Wni    = (const float*)d_in[6];
    const float* Wnj    = (const float*)d_in[7];
    const float* Woh    = (const float*)d_in[8];
    const float* boh    = (const float*)d_in[9];
    const float* Woe    = (const float*)d_in[10];
    const float* boe    = (const float*)d_in[11];
    const float* bn1_g  = (const float*)d_in[12];
    const float* bn1_b  = (const float*)d_in[13];
    const float* bn2_g  = (const float*)d_in[14];
    const float* bn2_b  = (const float*)d_in[15];
    const float* ln1_g  = (const float*)d_in[16];
    const float* ln1_b  = (const float*)d_in[17];
    const float* ln2_g  = (const float*)d_in[18];
    const float* ln2_b  = (const float*)d_in[19];
    const float* ffh_w1 = (const float*)d_in[20];
    const float* ffh_w3 = (const float*)d_in[21];
    const float* ffh_w2 = (const float*)d_in[22];
    const float* ffe_w1 = (const float*)d_in[23];
    const float* ffe_w3 = (const float*)d_in[24];
    const float* ffe_w2 = (const float*)d_in[25];
    float* out = (float*)d_out;

    float *h1, *h2, *qkv, *ao, *uth, *e1, *eW, *ev, *e2, *UT;
    __nv_bfloat16 *e1hi, *e1lo, *evhi, *evlo, *Shi, *Slo;
    __nv_bfloat16 *h1hi, *h1lo, *aohi, *aolo, *xhhi, *xhlo, *shhi, *shlo, *whi, *wlo;
    cudaGetSymbolAddress((void**)&h1, g_h1);
    cudaGetSymbolAddress((void**)&h2, g_h2);
    cudaGetSymbolAddress((void**)&qkv, g_qkv);
    cudaGetSymbolAddress((void**)&ao, g_ao);
    cudaGetSymbolAddress((void**)&uth, g_uth);
    cudaGetSymbolAddress((void**)&e1, g_e1);
    cudaGetSymbolAddress((void**)&eW, g_eW);
    cudaGetSymbolAddress((void**)&ev, g_ev);
    cudaGetSymbolAddress((void**)&e2, g_e2);
    cudaGetSymbolAddress((void**)&UT, g_UT);
    cudaGetSymbolAddress((void**)&e1hi, g_e1hi);
    cudaGetSymbolAddress((void**)&e1lo, g_e1lo);
    cudaGetSymbolAddress((void**)&evhi, g_evhi);
    cudaGetSymbolAddress((void**)&evlo, g_evlo);
    cudaGetSymbolAddress((void**)&Shi, g_Shi);
    cudaGetSymbolAddress((void**)&Slo, g_Slo);
    cudaGetSymbolAddress((void**)&h1hi, g_h1hi);
    cudaGetSymbolAddress((void**)&h1lo, g_h1lo);
    cudaGetSymbolAddress((void**)&aohi, g_aohi);
    cudaGetSymbolAddress((void**)&aolo, g_aolo);
    cudaGetSymbolAddress((void**)&xhhi, g_xhhi);
    cudaGetSymbolAddress((void**)&xhlo, g_xhlo);
    cudaGetSymbolAddress((void**)&shhi, g_shhi);
    cudaGetSymbolAddress((void**)&shlo, g_shlo);
    cudaGetSymbolAddress((void**)&whi, g_whi);
    cudaGetSymbolAddress((void**)&wlo, g_wlo);

    // weight pool offsets (transposed [N,K] bf16)
    const size_t O_Wq = 0, O_We = 1310720, O_Woh = 1572864, O_Woe = 1835008;
    const size_t O_fh13 = 2097152, O_fh2 = 4194304;
    const size_t O_fe13 = 5242880, O_fe2 = 7340032;

    dim3 tb(32, 8);
    wcvt<<<dim3(16, 16), tb>>>(Wq,  whi + 0,       wlo + 0,       512, 512);
    wcvt<<<dim3(16, 16), tb>>>(Wk,  whi + 262144,  wlo + 262144,  512, 512);
    wcvt<<<dim3(16, 16), tb>>>(Wv,  whi + 524288,  wlo + 524288,  512, 512);
    wcvt<<<dim3(16, 16), tb>>>(Wni, whi + 786432,  wlo + 786432,  512, 512);
    wcvt<<<dim3(16, 16), tb>>>(Wnj, whi + 1048576, wlo + 1048576, 512, 512);
    wcvt<<<dim3(16, 16), tb>>>(We,  whi + O_We,  wlo + O_We,  512, 512);
    wcvt<<<dim3(16, 16), tb>>>(Woh, whi + O_Woh, wlo + O_Woh, 512, 512);
    wcvt<<<dim3(16, 16), tb>>>(Woe, whi + O_Woe, wlo + O_Woe, 512, 512);
    wcvt<<<dim3(64, 16), tb>>>(ffh_w1, whi + O_fh13,           wlo + O_fh13,           512, 2048);
    wcvt<<<dim3(64, 16), tb>>>(ffh_w3, whi + O_fh13 + 1048576, wlo + O_fh13 + 1048576, 512, 2048);
    wcvt<<<dim3(16, 64), tb>>>(ffh_w2, whi + O_fh2, wlo + O_fh2, 2048, 512);
    wcvt<<<dim3(64, 16), tb>>>(ffe_w1, whi + O_fe13,           wlo + O_fe13,           512, 2048);
    wcvt<<<dim3(64, 16), tb>>>(ffe_w3, whi + O_fe13 + 1048576, wlo + O_fe13 + 1048576, 512, 2048);
    wcvt<<<dim3(16, 64), tb>>>(ffe_w2, whi + O_fe2, wlo + O_fe2, 2048, 512);

    // h1 = bn1(h), e1 = ln1(e)  (+ bf16 splits)
    bn_stats<<<2, 256>>>(h, bn1_g, bn1_b);
    bn_apply_cvt<<<HTOT / 4 / 256, 256>>>(h, h1, h1hi, h1lo);
    ln_cvt<<<EROWS, 128>>>(e, e1, e1hi, e1lo, ln1_g, ln1_b);

    // projections (fused N=2560) and edge projection
    tc_gemm<<<dim3(20, 2), 256>>>(h1hi, h1lo, whi, wlo, qkv, 256, QKVW, 512, nullptr, nullptr);
    tc_gemm<<<dim3(4, 256), 256>>>(e1hi, e1lo, whi + O_We, wlo + O_We, eW, EROWS, 512, 512, nullptr, nullptr);
    ev_add_cvt<<<(int)(ETOT / 4 / 256), 256>>>();

    attn_kernel<<<BSZ * NH * NT, 128>>>();
    cvt_split<<<HTOT / 4 / 256, 256>>>(ao, aohi, aolo, HTOT / 4);

    // h2 = h1 + ao@Woh + boh ; e2 = e1 + ev@Woe + boe
    tc_gemm<<<dim3(4, 2), 256>>>(aohi, aolo, whi + O_Woh, wlo + O_Woh, h2, 256, 512, 512, boh, h1);
    tc_gemm<<<dim3(4, 256), 256>>>(evhi, evlo, whi + O_Woe, wlo + O_Woe, e2, EROWS, 512, 512, boe, e1);

    // node FFN
    bn_stats<<<2, 256>>>(h2, bn2_g, bn2_b);
    bn_apply_cvt<<<HTOT / 4 / 256, 256>>>(h2, nullptr, xhhi, xhlo);
    tc_gemm<<<dim3(32, 2), 256>>>(xhhi, xhlo, whi + O_fh13, wlo + O_fh13, uth, 256, 4096, 512, nullptr, nullptr);
    silu_cvt<<<(256 * 512) / 256, 256>>>(uth, shhi, shlo, 256);
    tc_gemm<<<dim3(4, 2), 256>>>(shhi, shlo, whi + O_fh2, wlo + O_fh2, out, 256, 512, 2048, nullptr, h2);

    // edge FFN
    ln_cvt<<<EROWS, 128>>>(e2, nullptr, e1hi, e1lo, ln2_g, ln2_b);  // xe reuses e1 split buffers
    tc_gemm<<<dim3(32, 256), 256>>>(e1hi, e1lo, whi + O_fe13, wlo + O_fe13, UT, EROWS, 4096, 512, nullptr, nullptr);
    silu_cvt<<<(int)(((size_t)EROWS * 512) / 256), 256>>>(UT, Shi, Slo, EROWS);
    tc_gemm<<<dim3(4, 256), 256>>>(Shi, Slo, whi + O_fe2, wlo + O_fe2, eW, EROWS, 512, 2048, nullptr, e2);

    // symmetrize -> out
    sym_kernel<<<(int)(ETOT / 4 / 256), 256>>>(out + HTOT);
}